// round 10
// baseline (speedup 1.0000x reference)
#include <cuda_runtime.h>

#define BN 24
#define BM 128
#define BK 64
#define NITER 8
#define NFIX 12
#define NACT 12
#define PIF 3.14159274101257324f   // float32(np.pi)
#define BLOCK 512
#define WPB (BLOCK / 32)           // 16 batches (warps) per block

// ---------------------------------------------------------------------------
__device__ __forceinline__ float dot4(float4 a, float4 b) {
    return fmaf(a.x, b.x, fmaf(a.y, b.y, fmaf(a.z, b.z, a.w * b.w)));
}
__device__ __forceinline__ float2 mul2(float2 a, float s) {
    return make_float2(a.x * s, a.y * s);
}
__device__ __forceinline__ float2 fma2(float2 a, float s, float2 c) {
    return make_float2(fmaf(a.x, s, c.x), fmaf(a.y, s, c.y));
}
__device__ __forceinline__ float dot2(float2 a, float2 b) {
    return fmaf(a.x, b.x, a.y * b.y);
}
// full-warp sum (5-stage butterfly)
__device__ __forceinline__ float wsum32(float v) {
    v += __shfl_xor_sync(0xffffffffu, v, 16);
    v += __shfl_xor_sync(0xffffffffu, v, 8);
    v += __shfl_xor_sync(0xffffffffu, v, 4);
    v += __shfl_xor_sync(0xffffffffu, v, 2);
    v += __shfl_xor_sync(0xffffffffu, v, 1);
    return v;
}
// two independent warp sums, shfls interleaved
__device__ __forceinline__ void wsum32_2(float& a, float& b) {
    a += __shfl_xor_sync(0xffffffffu, a, 16); b += __shfl_xor_sync(0xffffffffu, b, 16);
    a += __shfl_xor_sync(0xffffffffu, a, 8);  b += __shfl_xor_sync(0xffffffffu, b, 8);
    a += __shfl_xor_sync(0xffffffffu, a, 4);  b += __shfl_xor_sync(0xffffffffu, b, 4);
    a += __shfl_xor_sync(0xffffffffu, a, 2);  b += __shfl_xor_sync(0xffffffffu, b, 2);
    a += __shfl_xor_sync(0xffffffffu, a, 1);  b += __shfl_xor_sync(0xffffffffu, b, 1);
}
__device__ __forceinline__ float out_angle(float co) {
    float c = fminf(fmaxf(-co, -1.0f + 1e-6f), 1.0f - 1e-6f);
    return acosf(c) / PIF;
}

// ---------------------------------------------------------------------------
// One WARP per batch element; lane owns comps 2*lane, 2*lane+1 (float2).
// ---------------------------------------------------------------------------
__global__ void __launch_bounds__(BLOCK) mix_kernel(
    const float* __restrict__ z,
    const float* __restrict__ S,
    const float* __restrict__ Vr,
    const int* __restrict__ isin,
    float* __restrict__ out,
    int B)
{
    // Only Gram rows 12..23 are needed in the hot path:
    // Gs2[r*BN + c] = G[12+r][c]
    __shared__ __align__(16) float Gs2[NACT * BN];

    const int tid  = threadIdx.x;
    const int lane = tid & 31;
    const int wid  = tid >> 5;            // 16 warps

    // ---- phase 0: 288 Gram entries, warp-cooperative (lanes span M=128) ----
    const float4* S4 = (const float4*)S;  // S4[i*32 + m4]
#pragma unroll
    for (int e = wid; e < NACT * BN; e += WPB) {
        int i = NFIX + e / BN, j = e % BN;
        float part = dot4(S4[i * 32 + lane], S4[j * 32 + lane]);
        float g = wsum32(part);
        if (lane == 0) Gs2[e] = g;
    }
    __syncthreads();

    int b = blockIdx.x * WPB + wid;
    if (b >= B) b = B - 1;    // duplicate work, deterministic

    const float2* vrow = (const float2*)Vr + (size_t)b * BN * 32;
    float*        outb = out + (size_t)b * BN;

    int ivn = (lane < BN) ? isin[b * BN + lane] : 0;
    unsigned mask = __ballot_sync(0xffffffffu, ivn > 0) & 0xFFFFFFu;

    // ---- v0 ----
    float2 f0  = vrow[lane];
    float  ss0 = wsum32(dot2(f0, f0));
    float2 v0  = mul2(f0, rsqrtf(fmaxf(ss0, 1e-30f)));

    if (mask == 0xFFFu) {
        // ================= FAST PATH: inputs are rows 0..11 =================
        float nv0 = wsum32(dot2(v0, v0));      // |v0|^2 (~1), row-0 output
        if (lane == 0) outb[0] = out_angle(nv0);

        float2 h[NACT];
#pragma unroll
        for (int ii = 0; ii < NACT; ii++)
            h[ii] = mul2(v0, Gs2[ii * BN + 0]);

        // fixed input rows 1..11 (independent -> ILP; one paired reduction each)
#pragma unroll
        for (int n = 1; n < NFIX; n++) {
            float2 f  = vrow[n * 32 + lane];
            float  ss = dot2(f, f);
            float  fv = dot2(f, v0);
            wsum32_2(ss, fv);
            float ww = fmaf(-fv * fv, 2.0f - nv0, ss);   // |f - fv*v0|^2
            float iu = rsqrtf(fmaxf(ww, 1e-24f));
            float2 u = mul2(fma2(v0, -fv, f), iu);
            float sz, cz;
            __sincosf(PIF * z[b * BN + n], &sz, &cz);
            float2 vv = fma2(v0, -cz, mul2(u, sz));
            // vv.v0 = -cz*|v0|^2 + sz*iu*fv*(1-|v0|^2): broadcast scalars only
            float co = fmaf(-cz, nv0, sz * iu * fv * (1.0f - nv0));
            if (lane == 0) outb[n] = out_angle(co);
#pragma unroll
            for (int ii = 0; ii < NACT; ii++)
                h[ii] = fma2(vv, Gs2[ii * BN + n], h[ii]);
        }

        // free rows 12..23 (paired reductions)
        float2 A[NACT];
#pragma unroll
        for (int jj = 0; jj < NACT; jj += 2) {
            float2 fa = vrow[(NFIX + jj) * 32 + lane];
            float2 fb = vrow[(NFIX + jj + 1) * 32 + lane];
            float  sa = dot2(fa, fa);
            float  sb = dot2(fb, fb);
            wsum32_2(sa, sb);
            A[jj]     = mul2(fa, rsqrtf(fmaxf(sa, 1e-30f)));
            A[jj + 1] = mul2(fb, rsqrtf(fmaxf(sb, 1e-30f)));
        }

        // ---- software-pipelined Gauss–Seidel: 8 sweeps x 12 steps ----
        // Invariant at loop head: p = h[ii] + sum_{jj!=ii} G[ii][jj]*A[jj]
        // with correct GS recency.
        float2 p;
        {
            const float4* gr = (const float4*)&Gs2[0 * BN + NFIX];
            float4 w0 = gr[0], w1 = gr[1], w2 = gr[2];
            const float wv[NACT] = { w0.x, w0.y, w0.z, w0.w,
                                     w1.x, w1.y, w1.z, w1.w,
                                     w2.x, w2.y, w2.z, w2.w };
            p = h[0];
#pragma unroll
            for (int jj = 1; jj < NACT; jj++) p = fma2(A[jj], wv[jj], p);
        }

        for (int t = 0; t < NITER; t++) {
#pragma unroll
            for (int ii = 0; ii < NACT; ii++) {
                // launch this step's reduction first...
                float s = wsum32(dot2(p, p));

                // ...its latency hidden by building next step's partial sum
                const int nx = (ii + 1) % NACT;
                const float4* gr = (const float4*)&Gs2[nx * BN + NFIX];
                float4 w0 = gr[0], w1 = gr[1], w2 = gr[2];
                const float wv[NACT] = { w0.x, w0.y, w0.z, w0.w,
                                         w1.x, w1.y, w1.z, w1.w,
                                         w2.x, w2.y, w2.z, w2.w };
                float2 q = h[nx];
#pragma unroll
                for (int jj = 0; jj < NACT; jj++) {
                    if (jj == nx || jj == ii) continue;
                    q = fma2(A[jj], wv[jj], q);
                }

                float  inv = -rsqrtf(s);      // s = |p|^2 > 0
                float2 An  = mul2(p, inv);
                A[ii] = An;
                p = fma2(An, wv[ii], q);
            }
        }

        // active outputs (paired reductions)
#pragma unroll
        for (int ii = 0; ii < NACT; ii += 2) {
            float c0 = dot2(A[ii], v0);
            float c1 = dot2(A[ii + 1], v0);
            wsum32_2(c0, c1);
            if (lane == 0) {
                outb[NFIX + ii]     = out_angle(c0);
                outb[NFIX + ii + 1] = out_angle(c1);
            }
        }
    } else {
        // ============ GENERIC PATH (any mask) — cold =========================
        // Per-warp full Gram into local memory (cold path, spills OK)
        float Gc[BN * BN];
#pragma unroll 1
        for (int e = 0; e < BN * BN; e++) {
            int i = e / BN, j = e % BN;
            float part = dot4(S4[i * 32 + lane], S4[j * 32 + lane]);
            Gc[e] = wsum32(part);
        }

        float2 Vl[BN];
        Vl[0] = v0;
        float nv0g = wsum32(dot2(v0, v0));
#pragma unroll 1
        for (int n = 1; n < BN; n++) {
            float2 f  = vrow[n * 32 + lane];
            float  ss = dot2(f, f);
            float  fv = dot2(f, v0);
            wsum32_2(ss, fv);
            float2 r = mul2(f, rsqrtf(fmaxf(ss, 1e-30f)));
            if ((mask >> n) & 1u) {
                float ww = fmaf(-fv * fv, 2.0f - nv0g, ss);
                float iu = rsqrtf(fmaxf(ww, 1e-24f));
                float2 u = mul2(fma2(v0, -fv, f), iu);
                float sz, cz;
                __sincosf(PIF * z[b * BN + n], &sz, &cz);
                Vl[n] = fma2(v0, -cz, mul2(u, sz));
            } else {
                Vl[n] = r;
            }
        }
#pragma unroll 1
        for (int t = 0; t < NITER; t++) {
#pragma unroll 1
            for (int i = 0; i < BN; i++) {
                if ((mask >> i) & 1u) continue;
                float2 acc = make_float2(0.f, 0.f);
#pragma unroll 1
                for (int n = 0; n < BN; n++)
                    acc = fma2(Vl[n], Gc[i * BN + n], acc);
                acc = fma2(Vl[i], -Gc[i * BN + i], acc);
                float s = wsum32(dot2(acc, acc));
                Vl[i] = mul2(acc, -rsqrtf(fmaxf(s, 1e-30f)));
            }
        }
#pragma unroll 1
        for (int n = 0; n < BN; n++) {
            float co = wsum32(dot2(Vl[n], v0));
            if (lane == 0) outb[n] = out_angle(co);
        }
    }
}

// ---------------------------------------------------------------------------
extern "C" void kernel_launch(void* const* d_in, const int* in_sizes, int n_in,
                              void* d_out, int out_size) {
    const float* z    = (const float*)d_in[0];   // (B, 24)
    const float* S    = (const float*)d_in[1];   // (24, 128)
    const float* Vr   = (const float*)d_in[2];   // (B, 24, 64)
    const int*   isin = (const int*)d_in[3];     // (B, 24)
    float*       out  = (float*)d_out;           // (B, 24)

    const int B = in_sizes[0] / BN;
    const int grid = (B + WPB - 1) / WPB;
    mix_kernel<<<grid, BLOCK>>>(z, S, Vr, isin, out, B);
}

// round 11
// speedup vs baseline: 1.5976x; 1.5976x over previous
#include <cuda_runtime.h>

#define BN 24
#define BM 128
#define BK 64
#define NITER 8
#define NFIX 12
#define NACT 12
#define PIF 3.14159274101257324f   // float32(np.pi)
#define BLOCK 256
#define GPB (BLOCK / 16)           // 16 batches (16-lane groups) per block

// ---------------------------------------------------------------------------
__device__ __forceinline__ float dot4(float4 a, float4 b) {
    return fmaf(a.x, b.x, fmaf(a.y, b.y, fmaf(a.z, b.z, a.w * b.w)));
}
__device__ __forceinline__ float4 mul4(float4 a, float s) {
    return make_float4(a.x * s, a.y * s, a.z * s, a.w * s);
}
__device__ __forceinline__ float4 fma4(float4 a, float s, float4 c) {
    return make_float4(fmaf(a.x, s, c.x), fmaf(a.y, s, c.y),
                       fmaf(a.z, s, c.z), fmaf(a.w, s, c.w));
}
// sum over 16-lane subgroup (xor 8,4,2,1 stays in group)
__device__ __forceinline__ float gsum16(float v) {
    v += __shfl_xor_sync(0xffffffffu, v, 8);
    v += __shfl_xor_sync(0xffffffffu, v, 4);
    v += __shfl_xor_sync(0xffffffffu, v, 2);
    v += __shfl_xor_sync(0xffffffffu, v, 1);
    return v;
}
__device__ __forceinline__ void gsum16_2(float& a, float& b) {
    a += __shfl_xor_sync(0xffffffffu, a, 8); b += __shfl_xor_sync(0xffffffffu, b, 8);
    a += __shfl_xor_sync(0xffffffffu, a, 4); b += __shfl_xor_sync(0xffffffffu, b, 4);
    a += __shfl_xor_sync(0xffffffffu, a, 2); b += __shfl_xor_sync(0xffffffffu, b, 2);
    a += __shfl_xor_sync(0xffffffffu, a, 1); b += __shfl_xor_sync(0xffffffffu, b, 1);
}
// full-warp sum (for the Gram prologue)
__device__ __forceinline__ float wsum32(float v) {
    v += __shfl_xor_sync(0xffffffffu, v, 16);
    return gsum16(v);
}
__device__ __forceinline__ float out_angle(float co) {
    float c = fminf(fmaxf(-co, -1.0f + 1e-6f), 1.0f - 1e-6f);
    return acosf(c) / PIF;
}

// ---------------------------------------------------------------------------
// One 16-lane group per batch element; lane owns comps 4*gl .. 4*gl+3.
// ---------------------------------------------------------------------------
__global__ void __launch_bounds__(BLOCK) mix_kernel(
    const float* __restrict__ z,
    const float* __restrict__ S,
    const float* __restrict__ Vr,
    const int* __restrict__ isin,
    float* __restrict__ out,
    int B)
{
    // Only Gram rows 12..23 are needed in the hot path:
    // Gs2[r*BN + c] = G[12+r][c]
    __shared__ __align__(16) float Gs2[NACT * BN];

    const int tid  = threadIdx.x;
    const int wlid = tid & 31;            // lane within warp
    const int wid  = tid >> 5;            // warp id (8 warps)

    // ---- phase 0: 288 Gram entries, warp-cooperative (lanes span M=128) ----
    const float4* S4 = (const float4*)S;  // S4[i*32 + m4]
#pragma unroll
    for (int e = wid; e < NACT * BN; e += BLOCK / 32) {
        int i = NFIX + e / BN, j = e % BN;
        float part = dot4(S4[i * 32 + wlid], S4[j * 32 + wlid]);
        float g = wsum32(part);
        if (wlid == 0) Gs2[e] = g;
    }
    __syncthreads();

    const int grp = tid >> 4;
    const int gl  = tid & 15;
    int b = blockIdx.x * GPB + grp;
    if (b >= B) b = B - 1;    // duplicate work, deterministic

    const float4* vrow = (const float4*)Vr + (size_t)b * BN * (BK / 4);
    float*        outb = out + (size_t)b * BN;

    unsigned mask = 0;
#pragma unroll
    for (int n = 0; n < BN; n++)
        mask |= (isin[b * BN + n] > 0) ? (1u << n) : 0u;

    // ---- v0 ----
    float4 f0  = vrow[gl];
    float  ss0 = gsum16(dot4(f0, f0));
    float4 v0  = mul4(f0, rsqrtf(fmaxf(ss0, 1e-30f)));

    if (mask == 0xFFFu) {
        // ================= FAST PATH: inputs are rows 0..11 =================
        float nv0 = gsum16(dot4(v0, v0));      // |v0|^2 (~1), row-0 output
        if (gl == 0) outb[0] = out_angle(nv0);

        float4 h[NACT];
#pragma unroll
        for (int ii = 0; ii < NACT; ii++)
            h[ii] = mul4(v0, Gs2[ii * BN + 0]);

        // fixed input rows 1..11
#pragma unroll
        for (int n = 1; n < NFIX; n++) {
            float4 f  = vrow[n * 16 + gl];
            float  ss = dot4(f, f);
            float  fv = dot4(f, v0);
            gsum16_2(ss, fv);
            float ww = fmaf(-fv * fv, 2.0f - nv0, ss);   // |f - fv*v0|^2
            float iu = rsqrtf(fmaxf(ww, 1e-24f));
            float4 u = mul4(fma4(v0, -fv, f), iu);
            float sz, cz;
            __sincosf(PIF * z[b * BN + n], &sz, &cz);
            float4 vv = fma4(v0, -cz, mul4(u, sz));
            float co = fmaf(-cz, nv0, sz * iu * fv * (1.0f - nv0));
            if (gl == 0) outb[n] = out_angle(co);
#pragma unroll
            for (int ii = 0; ii < NACT; ii++)
                h[ii] = fma4(vv, Gs2[ii * BN + n], h[ii]);
        }

        // free rows 12..23 (paired reductions)
        float4 A[NACT];
#pragma unroll
        for (int jj = 0; jj < NACT; jj += 2) {
            float4 fa = vrow[(NFIX + jj) * 16 + gl];
            float4 fb = vrow[(NFIX + jj + 1) * 16 + gl];
            float  sa = dot4(fa, fa);
            float  sb = dot4(fb, fb);
            gsum16_2(sa, sb);
            A[jj]     = mul4(fa, rsqrtf(fmaxf(sa, 1e-30f)));
            A[jj + 1] = mul4(fb, rsqrtf(fmaxf(sb, 1e-30f)));
        }

        // ---- Gauss–Seidel with recurrence-propagated norm ----
        // State: p = gradient vector of current row ii, s = |p|^2.
        // Per step: A[ii] = -rsqrt(s)*p;  p_next = q + w*A[ii]
        // where q = h[nx] + sum_{jj!=ii,nx} G[nx][jj]*A[jj] (all final values).
        // |p_next|^2 expands to qq - 2*w*r*qp + (w*r)^2*s, with qq=|q|^2,
        // qp=q.p — both reducible BEFORE s resolves. This removes the
        // butterfly from the serial s-chain (rsqrt + 2 FMA per step).
        float4 p;
        float  s;
        {
            const float4* gr = (const float4*)&Gs2[0 * BN + NFIX];
            float4 w0 = gr[0], w1 = gr[1], w2 = gr[2];
            const float wv[NACT] = { w0.x, w0.y, w0.z, w0.w,
                                     w1.x, w1.y, w1.z, w1.w,
                                     w2.x, w2.y, w2.z, w2.w };
            p = h[0];
#pragma unroll
            for (int jj = 1; jj < NACT; jj++) p = fma4(A[jj], wv[jj], p);
            s = gsum16(dot4(p, p));
        }

        for (int t = 0; t < NITER; t++) {
#pragma unroll
            for (int ii = 0; ii < NACT; ii++) {
                const float  r  = rsqrtf(s);       // s = |p|^2 > 0
                const float4 An = mul4(p, -r);
                A[ii] = An;

                // next row's partial sum (excludes A[ii]; all operands final)
                const int nx = (ii + 1) % NACT;
                const float4* gr = (const float4*)&Gs2[nx * BN + NFIX];
                float4 w0 = gr[0], w1 = gr[1], w2 = gr[2];
                const float wv[NACT] = { w0.x, w0.y, w0.z, w0.w,
                                         w1.x, w1.y, w1.z, w1.w,
                                         w2.x, w2.y, w2.z, w2.w };
                float4 q = h[nx];
#pragma unroll
                for (int jj = 0; jj < NACT; jj++) {
                    if (jj == nx || jj == ii) continue;
                    q = fma4(A[jj], wv[jj], q);
                }

                // reductions independent of r — overlap with rsqrt/scalar ops
                float qq = dot4(q, q);
                float qp = dot4(q, p);
                gsum16_2(qq, qp);

                const float w  = wv[ii];
                const float wr = w * r;
                // s_next = qq - 2*wr*qp + wr^2*s
                s = fmaf(wr * wr, s, fmaf(-2.0f * wr, qp, qq));
                p = fma4(An, w, q);
            }
        }

        // active outputs (paired reductions)
#pragma unroll
        for (int ii = 0; ii < NACT; ii += 2) {
            float c0 = dot4(A[ii], v0);
            float c1 = dot4(A[ii + 1], v0);
            gsum16_2(c0, c1);
            if (gl == 0) {
                outb[NFIX + ii]     = out_angle(c0);
                outb[NFIX + ii + 1] = out_angle(c1);
            }
        }
    } else {
        // ============ GENERIC PATH (any mask) — cold =========================
        float Gc[BN * BN];
#pragma unroll 1
        for (int e = 0; e < BN * BN; e++) {
            int i = e / BN, j = e % BN;
            float part = dot4(S4[i * 32 + gl],      S4[j * 32 + gl]) +
                         dot4(S4[i * 32 + 16 + gl], S4[j * 32 + 16 + gl]);
            Gc[e] = gsum16(part);
        }

        float4 Vl[BN];
        Vl[0] = v0;
        float nv0g = gsum16(dot4(v0, v0));
#pragma unroll 1
        for (int n = 1; n < BN; n++) {
            float4 f  = vrow[n * 16 + gl];
            float  ss = dot4(f, f);
            float  fv = dot4(f, v0);
            gsum16_2(ss, fv);
            float4 r = mul4(f, rsqrtf(fmaxf(ss, 1e-30f)));
            if ((mask >> n) & 1u) {
                float ww = fmaf(-fv * fv, 2.0f - nv0g, ss);
                float iu = rsqrtf(fmaxf(ww, 1e-24f));
                float4 u = mul4(fma4(v0, -fv, f), iu);
                float sz, cz;
                __sincosf(PIF * z[b * BN + n], &sz, &cz);
                Vl[n] = fma4(v0, -cz, mul4(u, sz));
            } else {
                Vl[n] = r;
            }
        }
#pragma unroll 1
        for (int t = 0; t < NITER; t++) {
#pragma unroll 1
            for (int i = 0; i < BN; i++) {
                if ((mask >> i) & 1u) continue;
                float4 acc = make_float4(0.f, 0.f, 0.f, 0.f);
#pragma unroll 1
                for (int n = 0; n < BN; n++)
                    acc = fma4(Vl[n], Gc[i * BN + n], acc);
                acc = fma4(Vl[i], -Gc[i * BN + i], acc);
                float sg = gsum16(dot4(acc, acc));
                Vl[i] = mul4(acc, -rsqrtf(fmaxf(sg, 1e-30f)));
            }
        }
#pragma unroll 1
        for (int n = 0; n < BN; n++) {
            float co = gsum16(dot4(Vl[n], v0));
            if (gl == 0) outb[n] = out_angle(co);
        }
    }
}

// ---------------------------------------------------------------------------
extern "C" void kernel_launch(void* const* d_in, const int* in_sizes, int n_in,
                              void* d_out, int out_size) {
    const float* z    = (const float*)d_in[0];   // (B, 24)
    const float* S    = (const float*)d_in[1];   // (24, 128)
    const float* Vr   = (const float*)d_in[2];   // (B, 24, 64)
    const int*   isin = (const int*)d_in[3];     // (B, 24)
    float*       out  = (float*)d_out;           // (B, 24)

    const int B = in_sizes[0] / BN;
    const int grid = (B + GPB - 1) / GPB;
    mix_kernel<<<grid, BLOCK>>>(z, S, Vr, isin, out, B);
}